// round 15
// baseline (speedup 1.0000x reference)
// EDESC_18296560681209 — fused (z@D) per-cluster sum-of-squares + row-normalize + z passthrough.
// sm_103 BASE target (no tcgen05). R11/R14 GEMM byte-identical (at HMMA/clock floor).
// R15: z fp32 passthrough moved OFF the SM path onto a copy-engine memcpy node on a forked
// capture branch, hidden under the 5.2ms compute-bound GEMM. conv now moves 1.2GB (was 1.74).
#include <cuda_runtime.h>
#include <cuda_fp16.h>
#include <cstdint>
#include <cstddef>

#define NROWS 16384
#define NZ    8192
#define NCLU  16

// GEMM tiling: CTA 128x128, 8 warps (2 m x 4 n), warp tile 64x32, k-chunk 64
#define NK (NZ / 64)                   // 128 k-chunks
#define STAGES 2
#define LDB 144                        // smem row stride BYTES (64 halves + 8 pad) — conflict-free ldsm
#define TILE_BYTES (128 * LDB)         // 18432 per operand tile
#define STAGE_BYTES (2 * TILE_BYTES)   // 36864
#define GEMM_SMEM (STAGES * STAGE_BYTES) // 73728 -> 2 CTAs/SM

// ---------------- device scratch (static; allocation-free rule) ----------------
__device__ __align__(256) __half g_zh[(size_t)NROWS * NZ];   // z fp16 row-major
__device__ __align__(256) __half g_Dt[(size_t)NZ * NZ];      // D^T fp16 row-major [n][k]
__device__ float g_part[(size_t)NROWS * 64];                  // per (row, 128col-n-tile) partials

// ---------------- helpers ----------------
__device__ __forceinline__ uint32_t smem_u32(const void* p) {
    uint32_t a;
    asm("{ .reg .u64 t; cvta.to.shared.u64 t, %1; cvt.u32.u64 %0, t; }" : "=r"(a) : "l"(p));
    return a;
}
__device__ __forceinline__ void cpasync16(uint32_t dst, const void* src) {
    asm volatile("cp.async.cg.shared.global [%0], [%1], 16;" :: "r"(dst), "l"(src));
}
#define CP_COMMIT()  asm volatile("cp.async.commit_group;" ::: "memory")
#define CP_WAIT0()   asm volatile("cp.async.wait_group 0;" ::: "memory")

__device__ __forceinline__ void ldsm4(uint32_t& r0, uint32_t& r1, uint32_t& r2, uint32_t& r3, uint32_t a) {
    asm volatile("ldmatrix.sync.aligned.m8n8.x4.shared.b16 {%0,%1,%2,%3}, [%4];"
                 : "=r"(r0), "=r"(r1), "=r"(r2), "=r"(r3) : "r"(a));
}
// m16n8k16 fp16 x fp16 -> fp32 accumulate
__device__ __forceinline__ void mma_f(float& d0, float& d1, float& d2, float& d3,
                                      uint32_t a0, uint32_t a1, uint32_t a2, uint32_t a3,
                                      uint32_t b0, uint32_t b1) {
    asm volatile("mma.sync.aligned.m16n8k16.row.col.f32.f16.f16.f32 "
                 "{%0,%1,%2,%3}, {%4,%5,%6,%7}, {%8,%9}, {%0,%1,%2,%3};"
                 : "+f"(d0), "+f"(d1), "+f"(d2), "+f"(d3)
                 : "r"(a0), "r"(a1), "r"(a2), "r"(a3), "r"(b0), "r"(b1));
}

// ---------------- kernel 1: conversions (z passthrough handled by CE memcpy) ----------------
// blocks [0, NZBLK): z -> fp16 (g_zh) only
// blocks [NZBLK, NZBLK+NDBLK): D -> fp16 transposed (g_Dt); 16384 = 128 kb x 128 nb
#define NZBLK 65536
#define NDBLK 16384
__global__ __launch_bounds__(256) void conv_lite(const float* __restrict__ z,
                                                 const float* __restrict__ Dm) {
    const int b = blockIdx.x;
    if (b < NZBLK) {
        const size_t t = (size_t)b * 256 + threadIdx.x;
        const size_t base = t * 8;
        const float4* src = reinterpret_cast<const float4*>(z + base);
        float4 v0 = __ldcs(src + 0);           // read-once (CE copy is the other reader)
        float4 v1 = __ldcs(src + 1);
        __half2 h[4];
        h[0] = __floats2half2_rn(v0.x, v0.y);
        h[1] = __floats2half2_rn(v0.z, v0.w);
        h[2] = __floats2half2_rn(v1.x, v1.y);
        h[3] = __floats2half2_rn(v1.z, v1.w);
        *reinterpret_cast<uint4*>(g_zh + base) = *reinterpret_cast<uint4*>(h);
    } else {
        __shared__ __half t[64][65];
        const int db = b - NZBLK;              // 0..16383 = 128 kb x 128 nb
        const int kb = (db & 127) * 64, nb = (db >> 7) * 64;
        const int c = threadIdx.x & 63, rq = threadIdx.x >> 6;
#pragma unroll
        for (int i = 0; i < 16; ++i) {
            int r = i * 4 + rq;
            t[r][c] = __float2half_rn(__ldcs(Dm + (size_t)(kb + r) * NZ + nb + c));
        }
        __syncthreads();
#pragma unroll
        for (int i = 0; i < 16; ++i) {
            int r = i * 4 + rq;
            g_Dt[(size_t)(nb + r) * NZ + kb + c] = t[c][r];
        }
    }
}

// ---------------- kernel 2: fused GEMM + per-tile sum-of-squares (R11, unchanged) ----------------
__global__ __launch_bounds__(256, 2) void gemm_k() {
    extern __shared__ unsigned char smem[];
    const uint32_t smem_b = smem_u32(smem);

    // 8192 CTAs = 128 m-tiles x 64 n-tiles; n grouped by 16 for L2 reuse
    const int g = blockIdx.x;
    const int ng = g >> 11;
    const int rem = g & 2047;
    const int m = rem >> 4;
    const int n = ng * 16 + (rem & 15);

    const int tid = threadIdx.x;
    const int wid = tid >> 5;
    const int lane = tid & 31;
    const int wm = wid & 1;
    const int wn = wid >> 1;
    const int lt = lane >> 3;       // ldmatrix tile id 0..3
    const int lr = lane & 7;

    const __half* gA = g_zh + (size_t)m * 128 * NZ;
    const __half* gB = g_Dt + (size_t)n * 128 * NZ;

    // A (row-major [m][k]): lt0 r0-7/k0-7, lt1 r8-15/k0-7, lt2 r0-7/k8-15, lt3 r8-15/k8-15
    const uint32_t aOff = (uint32_t)((wm * 64 + (lt & 1) * 8 + lr) * LDB + (lt >> 1) * 16);
    // B ([n][k] storage, NON-trans): lt0 n0-7/k0-7, lt1 n0-7/k8-15, lt2 n8-15/k0-7, lt3 n8-15/k8-15
    const uint32_t bOff = (uint32_t)((wn * 32 + (lt >> 1) * 8 + lr) * LDB + (lt & 1) * 16);

    float accf[4][4][4];            // fp32 accumulators: [mi][ni][d0..d3]
#pragma unroll
    for (int i = 0; i < 4; ++i)
#pragma unroll
        for (int j = 0; j < 4; ++j)
#pragma unroll
            for (int e = 0; e < 4; ++e) accf[i][j][e] = 0.0f;

    auto issue_load = [&](int kc, int st) {
        const uint32_t sA = smem_b + st * STAGE_BYTES;
        const uint32_t sB = sA + TILE_BYTES;
        const __half* pa = gA + kc * 64;
        const __half* pb = gB + kc * 64;
#pragma unroll
        for (int i = 0; i < 4; ++i) {
            int c = tid + i * 256;
            int row = c >> 3, seg = c & 7;
            cpasync16(sA + row * LDB + seg * 16, pa + (size_t)row * NZ + seg * 8);
            cpasync16(sB + row * LDB + seg * 16, pb + (size_t)row * NZ + seg * 8);
        }
    };

    // prologue: chunk 0 in flight
    issue_load(0, 0); CP_COMMIT();

#pragma unroll 1
    for (int kc = 0; kc < NK; ++kc) {
        CP_WAIT0();                 // own copies of chunk kc complete
        __syncthreads();            // all warps finished compute(kc-1); chunk-kc data visible
        if (kc + 1 < NK) { issue_load(kc + 1, (kc + 1) & 1); }
        CP_COMMIT();

        const int st = kc & 1;
        const uint32_t sA = smem_b + st * STAGE_BYTES + aOff;
        const uint32_t sB = smem_b + st * STAGE_BYTES + TILE_BYTES + bOff;

#pragma unroll
        for (int ks = 0; ks < 4; ++ks) {
            uint32_t a[4][4];
#pragma unroll
            for (int mi = 0; mi < 4; ++mi)
                ldsm4(a[mi][0], a[mi][1], a[mi][2], a[mi][3], sA + mi * (16 * LDB) + ks * 32);
            uint32_t b[4][2];
            ldsm4(b[0][0], b[0][1], b[1][0], b[1][1], sB + ks * 32);
            ldsm4(b[2][0], b[2][1], b[3][0], b[3][1], sB + 16 * LDB + ks * 32);
#pragma unroll
            for (int mi = 0; mi < 4; ++mi)
#pragma unroll
                for (int ni = 0; ni < 4; ++ni)
                    mma_f(accf[mi][ni][0], accf[mi][ni][1], accf[mi][ni][2], accf[mi][ni][3],
                          a[mi][0], a[mi][1], a[mi][2], a[mi][3], b[ni][0], b[ni][1]);
        }
        // no end-of-loop barrier: top wait0+BAR of next iteration orders everything
    }

    // ---- epilogue: per-row sum of squares from fragments ----
    __syncthreads();                               // drain reads before smem reuse
    float* red = reinterpret_cast<float*>(smem);   // [128][4]
#pragma unroll
    for (int mi = 0; mi < 4; ++mi) {
        float slo = 0.0f, shi = 0.0f;
#pragma unroll
        for (int ni = 0; ni < 4; ++ni) {
            slo = fmaf(accf[mi][ni][0], accf[mi][ni][0], slo);
            slo = fmaf(accf[mi][ni][1], accf[mi][ni][1], slo);
            shi = fmaf(accf[mi][ni][2], accf[mi][ni][2], shi);
            shi = fmaf(accf[mi][ni][3], accf[mi][ni][3], shi);
        }
        slo += __shfl_xor_sync(0xffffffffu, slo, 1);
        slo += __shfl_xor_sync(0xffffffffu, slo, 2);
        shi += __shfl_xor_sync(0xffffffffu, shi, 1);
        shi += __shfl_xor_sync(0xffffffffu, shi, 2);
        if ((lane & 3) == 0) {
            int row = wm * 64 + mi * 16 + (lane >> 2);
            red[row * 4 + wn] = slo;
            red[(row + 8) * 4 + wn] = shi;
        }
    }
    __syncthreads();
    if (tid < 128) {
        float s = red[tid * 4 + 0] + red[tid * 4 + 1] + red[tid * 4 + 2] + red[tid * 4 + 3];
        g_part[(size_t)(m * 128 + tid) * 64 + n] = s;
    }
}

// ---------------- kernel 3: finalize s = (s + eta*d) / rowsum ----------------
__global__ __launch_bounds__(256) void fin_k(float* __restrict__ outs) {
    const int row = blockIdx.x * 256 + threadIdx.x;
    const float4* p = reinterpret_cast<const float4*>(g_part + (size_t)row * 64);
    float s[16];
    float sum = 0.0f;
#pragma unroll
    for (int c = 0; c < 16; ++c) {
        float4 v = p[c];
        s[c] = v.x + v.y + v.z + v.w + 2560.0f;   // + ETA * D_SUB
        sum += s[c];
    }
    const float inv = 1.0f / sum;
    float4* op = reinterpret_cast<float4*>(outs + (size_t)row * NCLU);
#pragma unroll
    for (int q = 0; q < 4; ++q)
        op[q] = make_float4(s[4 * q] * inv, s[4 * q + 1] * inv, s[4 * q + 2] * inv, s[4 * q + 3] * inv);
}

// ---------------- launch ----------------
extern "C" void kernel_launch(void* const* d_in, const int* in_sizes, int n_in,
                              void* d_out, int out_size) {
    const float* z  = (const float*)d_in[0];
    const float* Dm = (const float*)d_in[1];
    float* out = (float*)d_out;

    // one-time host-side infra (created on the uncaptured correctness call; no device mem)
    static cudaStream_t s2 = nullptr;
    static cudaEvent_t evFork = nullptr, evJoin = nullptr;
    if (!s2) {
        cudaStreamCreateWithFlags(&s2, cudaStreamNonBlocking);
        cudaEventCreateWithFlags(&evFork, cudaEventDisableTiming);
        cudaEventCreateWithFlags(&evJoin, cudaEventDisableTiming);
    }

    cudaFuncSetAttribute(gemm_k, cudaFuncAttributeMaxDynamicSharedMemorySize, GEMM_SMEM);

    // fork a parallel branch: copy-engine moves the z fp32 passthrough while SMs run conv+GEMM
    cudaEventRecord(evFork, 0);
    cudaStreamWaitEvent(s2, evFork, 0);
    cudaMemcpyAsync(out + (size_t)NROWS * NCLU, z,
                    (size_t)NROWS * NZ * sizeof(float), cudaMemcpyDeviceToDevice, s2);
    cudaEventRecord(evJoin, s2);

    conv_lite<<<NZBLK + NDBLK, 256>>>(z, Dm);
    gemm_k<<<8192, 256, GEMM_SMEM>>>();
    fin_k<<<NROWS / 256, 256>>>(out);

    // join: the copy must complete within this launch's graph
    cudaStreamWaitEvent(0, evJoin, 0);
}

// round 16
// speedup vs baseline: 1.0617x; 1.0617x over previous
// EDESC_18296560681209 — fused (z@D) per-cluster sum-of-squares + row-normalize + z passthrough.
// sm_103 BASE target (no tcgen05). R14 conv (SM passthrough; CE-copy overlap regressed —
// GEMM is power/clock-coupled). R16: GEMM split into two half-grid launches (m 0-63, 64-127)
// -> 4 launches/replay puts ncu's "-s 5 -c 1" capture ON the GEMM for the first time;
// cost bounded (~neutral: two half-tails == one full tail). Math byte-identical.
#include <cuda_runtime.h>
#include <cuda_fp16.h>
#include <cstdint>
#include <cstddef>

#define NROWS 16384
#define NZ    8192
#define NCLU  16

// GEMM tiling: CTA 128x128, 8 warps (2 m x 4 n), warp tile 64x32, k-chunk 64
#define NK (NZ / 64)                   // 128 k-chunks
#define STAGES 2
#define LDB 144                        // smem row stride BYTES (64 halves + 8 pad) — conflict-free ldsm
#define TILE_BYTES (128 * LDB)         // 18432 per operand tile
#define STAGE_BYTES (2 * TILE_BYTES)   // 36864
#define GEMM_SMEM (STAGES * STAGE_BYTES) // 73728 -> 2 CTAs/SM

// ---------------- device scratch (static; allocation-free rule) ----------------
__device__ __align__(256) __half g_zh[(size_t)NROWS * NZ];   // z fp16 row-major
__device__ __align__(256) __half g_Dt[(size_t)NZ * NZ];      // D^T fp16 row-major [n][k]
__device__ float g_part[(size_t)NROWS * 64];                  // per (row, 128col-n-tile) partials

// ---------------- helpers ----------------
__device__ __forceinline__ uint32_t smem_u32(const void* p) {
    uint32_t a;
    asm("{ .reg .u64 t; cvta.to.shared.u64 t, %1; cvt.u32.u64 %0, t; }" : "=r"(a) : "l"(p));
    return a;
}
__device__ __forceinline__ void cpasync16(uint32_t dst, const void* src) {
    asm volatile("cp.async.cg.shared.global [%0], [%1], 16;" :: "r"(dst), "l"(src));
}
#define CP_COMMIT()  asm volatile("cp.async.commit_group;" ::: "memory")
#define CP_WAIT0()   asm volatile("cp.async.wait_group 0;" ::: "memory")

__device__ __forceinline__ void ldsm4(uint32_t& r0, uint32_t& r1, uint32_t& r2, uint32_t& r3, uint32_t a) {
    asm volatile("ldmatrix.sync.aligned.m8n8.x4.shared.b16 {%0,%1,%2,%3}, [%4];"
                 : "=r"(r0), "=r"(r1), "=r"(r2), "=r"(r3) : "r"(a));
}
// m16n8k16 fp16 x fp16 -> fp32 accumulate
__device__ __forceinline__ void mma_f(float& d0, float& d1, float& d2, float& d3,
                                      uint32_t a0, uint32_t a1, uint32_t a2, uint32_t a3,
                                      uint32_t b0, uint32_t b1) {
    asm volatile("mma.sync.aligned.m16n8k16.row.col.f32.f16.f16.f32 "
                 "{%0,%1,%2,%3}, {%4,%5,%6,%7}, {%8,%9}, {%0,%1,%2,%3};"
                 : "+f"(d0), "+f"(d1), "+f"(d2), "+f"(d3)
                 : "r"(a0), "r"(a1), "r"(a2), "r"(a3), "r"(b0), "r"(b1));
}

// ---------------- kernel 1: merged conversions (R14) ----------------
// blocks [0, NZBLK): z -> fp16 (g_zh) + fp32 passthrough (outz), streaming hints
// blocks [NZBLK, NZBLK+NDBLK): D -> fp16 transposed (g_Dt); 16384 = 128 kb x 128 nb
#define NZBLK 65536
#define NDBLK 16384
__global__ __launch_bounds__(256) void conv_all(const float* __restrict__ z,
                                                const float* __restrict__ Dm,
                                                float* __restrict__ outz) {
    const int b = blockIdx.x;
    if (b < NZBLK) {
        const size_t t = (size_t)b * 256 + threadIdx.x;
        const size_t base = t * 8;
        const float4* src = reinterpret_cast<const float4*>(z + base);
        float4 v0 = __ldcs(src + 0);           // read-once: don't pollute L2
        float4 v1 = __ldcs(src + 1);
        float4* dst = reinterpret_cast<float4*>(outz + base);
        __stcs(dst + 0, v0);                   // write-once, never re-read
        __stcs(dst + 1, v1);
        __half2 h[4];
        h[0] = __floats2half2_rn(v0.x, v0.y);
        h[1] = __floats2half2_rn(v0.z, v0.w);
        h[2] = __floats2half2_rn(v1.x, v1.y);
        h[3] = __floats2half2_rn(v1.z, v1.w);
        *reinterpret_cast<uint4*>(g_zh + base) = *reinterpret_cast<uint4*>(h);
    } else {
        __shared__ __half t[64][65];
        const int db = b - NZBLK;              // 0..16383 = 128 kb x 128 nb
        const int kb = (db & 127) * 64, nb = (db >> 7) * 64;
        const int c = threadIdx.x & 63, rq = threadIdx.x >> 6;
#pragma unroll
        for (int i = 0; i < 16; ++i) {
            int r = i * 4 + rq;
            t[r][c] = __float2half_rn(__ldcs(Dm + (size_t)(kb + r) * NZ + nb + c));
        }
        __syncthreads();
#pragma unroll
        for (int i = 0; i < 16; ++i) {
            int r = i * 4 + rq;
            g_Dt[(size_t)(nb + r) * NZ + kb + c] = t[c][r];
        }
    }
}

// ---------------- kernel 2: fused GEMM + per-tile sum-of-squares (R11 math, half-grid) ----------------
// grid 4096 = 64 m-tiles x 64 n-tiles; m = m0 + local. n grouped by 16 for L2 reuse.
__global__ __launch_bounds__(256, 2) void gemm_k(int m0) {
    extern __shared__ unsigned char smem[];
    const uint32_t smem_b = smem_u32(smem);

    const int g = blockIdx.x;
    const int ng = g >> 10;               // 0..3
    const int rem = g & 1023;
    const int m = m0 + (rem >> 4);        // m0..m0+63
    const int n = ng * 16 + (rem & 15);   // 0..63

    const int tid = threadIdx.x;
    const int wid = tid >> 5;
    const int lane = tid & 31;
    const int wm = wid & 1;
    const int wn = wid >> 1;
    const int lt = lane >> 3;       // ldmatrix tile id 0..3
    const int lr = lane & 7;

    const __half* gA = g_zh + (size_t)m * 128 * NZ;
    const __half* gB = g_Dt + (size_t)n * 128 * NZ;

    // A (row-major [m][k]): lt0 r0-7/k0-7, lt1 r8-15/k0-7, lt2 r0-7/k8-15, lt3 r8-15/k8-15
    const uint32_t aOff = (uint32_t)((wm * 64 + (lt & 1) * 8 + lr) * LDB + (lt >> 1) * 16);
    // B ([n][k] storage, NON-trans): lt0 n0-7/k0-7, lt1 n0-7/k8-15, lt2 n8-15/k0-7, lt3 n8-15/k8-15
    const uint32_t bOff = (uint32_t)((wn * 32 + (lt >> 1) * 8 + lr) * LDB + (lt & 1) * 16);

    float accf[4][4][4];            // fp32 accumulators: [mi][ni][d0..d3]
#pragma unroll
    for (int i = 0; i < 4; ++i)
#pragma unroll
        for (int j = 0; j < 4; ++j)
#pragma unroll
            for (int e = 0; e < 4; ++e) accf[i][j][e] = 0.0f;

    auto issue_load = [&](int kc, int st) {
        const uint32_t sA = smem_b + st * STAGE_BYTES;
        const uint32_t sB = sA + TILE_BYTES;
        const __half* pa = gA + kc * 64;
        const __half* pb = gB + kc * 64;
#pragma unroll
        for (int i = 0; i < 4; ++i) {
            int c = tid + i * 256;
            int row = c >> 3, seg = c & 7;
            cpasync16(sA + row * LDB + seg * 16, pa + (size_t)row * NZ + seg * 8);
            cpasync16(sB + row * LDB + seg * 16, pb + (size_t)row * NZ + seg * 8);
        }
    };

    // prologue: chunk 0 in flight
    issue_load(0, 0); CP_COMMIT();

#pragma unroll 1
    for (int kc = 0; kc < NK; ++kc) {
        CP_WAIT0();                 // own copies of chunk kc complete
        __syncthreads();            // all warps finished compute(kc-1); chunk-kc data visible
        if (kc + 1 < NK) { issue_load(kc + 1, (kc + 1) & 1); }
        CP_COMMIT();

        const int st = kc & 1;
        const uint32_t sA = smem_b + st * STAGE_BYTES + aOff;
        const uint32_t sB = smem_b + st * STAGE_BYTES + TILE_BYTES + bOff;

#pragma unroll
        for (int ks = 0; ks < 4; ++ks) {
            uint32_t a[4][4];
#pragma unroll
            for (int mi = 0; mi < 4; ++mi)
                ldsm4(a[mi][0], a[mi][1], a[mi][2], a[mi][3], sA + mi * (16 * LDB) + ks * 32);
            uint32_t b[4][2];
            ldsm4(b[0][0], b[0][1], b[1][0], b[1][1], sB + ks * 32);
            ldsm4(b[2][0], b[2][1], b[3][0], b[3][1], sB + 16 * LDB + ks * 32);
#pragma unroll
            for (int mi = 0; mi < 4; ++mi)
#pragma unroll
                for (int ni = 0; ni < 4; ++ni)
                    mma_f(accf[mi][ni][0], accf[mi][ni][1], accf[mi][ni][2], accf[mi][ni][3],
                          a[mi][0], a[mi][1], a[mi][2], a[mi][3], b[ni][0], b[ni][1]);
        }
        // no end-of-loop barrier: top wait0+BAR of next iteration orders everything
    }

    // ---- epilogue: per-row sum of squares from fragments ----
    __syncthreads();                               // drain reads before smem reuse
    float* red = reinterpret_cast<float*>(smem);   // [128][4]
#pragma unroll
    for (int mi = 0; mi < 4; ++mi) {
        float slo = 0.0f, shi = 0.0f;
#pragma unroll
        for (int ni = 0; ni < 4; ++ni) {
            slo = fmaf(accf[mi][ni][0], accf[mi][ni][0], slo);
            slo = fmaf(accf[mi][ni][1], accf[mi][ni][1], slo);
            shi = fmaf(accf[mi][ni][2], accf[mi][ni][2], shi);
            shi = fmaf(accf[mi][ni][3], accf[mi][ni][3], shi);
        }
        slo += __shfl_xor_sync(0xffffffffu, slo, 1);
        slo += __shfl_xor_sync(0xffffffffu, slo, 2);
        shi += __shfl_xor_sync(0xffffffffu, shi, 1);
        shi += __shfl_xor_sync(0xffffffffu, shi, 2);
        if ((lane & 3) == 0) {
            int row = wm * 64 + mi * 16 + (lane >> 2);
            red[row * 4 + wn] = slo;
            red[(row + 8) * 4 + wn] = shi;
        }
    }
    __syncthreads();
    if (tid < 128) {
        float s = red[tid * 4 + 0] + red[tid * 4 + 1] + red[tid * 4 + 2] + red[tid * 4 + 3];
        g_part[(size_t)(m * 128 + tid) * 64 + n] = s;
    }
}

// ---------------- kernel 3: finalize s = (s + eta*d) / rowsum ----------------
__global__ __launch_bounds__(256) void fin_k(float* __restrict__ outs) {
    const int row = blockIdx.x * 256 + threadIdx.x;
    const float4* p = reinterpret_cast<const float4*>(g_part + (size_t)row * 64);
    float s[16];
    float sum = 0.0f;
#pragma unroll
    for (int c = 0; c < 16; ++c) {
        float4 v = p[c];
        s[c] = v.x + v.y + v.z + v.w + 2560.0f;   // + ETA * D_SUB
        sum += s[c];
    }
    const float inv = 1.0f / sum;
    float4* op = reinterpret_cast<float4*>(outs + (size_t)row * NCLU);
#pragma unroll
    for (int q = 0; q < 4; ++q)
        op[q] = make_float4(s[4 * q] * inv, s[4 * q + 1] * inv, s[4 * q + 2] * inv, s[4 * q + 3] * inv);
}

// ---------------- launch ----------------
extern "C" void kernel_launch(void* const* d_in, const int* in_sizes, int n_in,
                              void* d_out, int out_size) {
    const float* z  = (const float*)d_in[0];
    const float* Dm = (const float*)d_in[1];
    float* out = (float*)d_out;

    cudaFuncSetAttribute(gemm_k, cudaFuncAttributeMaxDynamicSharedMemorySize, GEMM_SMEM);

    conv_all<<<NZBLK + NDBLK, 256>>>(z, Dm, out + (size_t)NROWS * NCLU);
    gemm_k<<<4096, 256, GEMM_SMEM>>>(0);    // m-tiles 0..63
    gemm_k<<<4096, 256, GEMM_SMEM>>>(64);   // m-tiles 64..127
    fin_k<<<NROWS / 256, 256>>>(out);
}

// round 17
// speedup vs baseline: 1.0667x; 1.0047x over previous
// EDESC_18296560681209 — fused (z@D) per-cluster sum-of-squares + row-normalize + z passthrough.
// sm_103 BASE target (no tcgen05). R16 structure (2 half-grid GEMM launches — locality win).
// R17: n-grouping widened 4x16 -> 2x32 per half-launch: B group working set 64MB + A wave
// ~37MB stays L2-resident while A re-fetch drops 4x -> 2x  =>  GEMM DRAM traffic ~1.28GB ->
// ~0.77GB. Under the measured power/clock coupling (R15: +210GB/s cost 340us) predict -100us+.
#include <cuda_runtime.h>
#include <cuda_fp16.h>
#include <cstdint>
#include <cstddef>

#define NROWS 16384
#define NZ    8192
#define NCLU  16

// GEMM tiling: CTA 128x128, 8 warps (2 m x 4 n), warp tile 64x32, k-chunk 64
#define NK (NZ / 64)                   // 128 k-chunks
#define STAGES 2
#define LDB 144                        // smem row stride BYTES (64 halves + 8 pad) — conflict-free ldsm
#define TILE_BYTES (128 * LDB)         // 18432 per operand tile
#define STAGE_BYTES (2 * TILE_BYTES)   // 36864
#define GEMM_SMEM (STAGES * STAGE_BYTES) // 73728 -> 2 CTAs/SM

// ---------------- device scratch (static; allocation-free rule) ----------------
__device__ __align__(256) __half g_zh[(size_t)NROWS * NZ];   // z fp16 row-major
__device__ __align__(256) __half g_Dt[(size_t)NZ * NZ];      // D^T fp16 row-major [n][k]
__device__ float g_part[(size_t)NROWS * 64];                  // per (row, 128col-n-tile) partials

// ---------------- helpers ----------------
__device__ __forceinline__ uint32_t smem_u32(const void* p) {
    uint32_t a;
    asm("{ .reg .u64 t; cvta.to.shared.u64 t, %1; cvt.u32.u64 %0, t; }" : "=r"(a) : "l"(p));
    return a;
}
__device__ __forceinline__ void cpasync16(uint32_t dst, const void* src) {
    asm volatile("cp.async.cg.shared.global [%0], [%1], 16;" :: "r"(dst), "l"(src));
}
#define CP_COMMIT()  asm volatile("cp.async.commit_group;" ::: "memory")
#define CP_WAIT0()   asm volatile("cp.async.wait_group 0;" ::: "memory")

__device__ __forceinline__ void ldsm4(uint32_t& r0, uint32_t& r1, uint32_t& r2, uint32_t& r3, uint32_t a) {
    asm volatile("ldmatrix.sync.aligned.m8n8.x4.shared.b16 {%0,%1,%2,%3}, [%4];"
                 : "=r"(r0), "=r"(r1), "=r"(r2), "=r"(r3) : "r"(a));
}
// m16n8k16 fp16 x fp16 -> fp32 accumulate
__device__ __forceinline__ void mma_f(float& d0, float& d1, float& d2, float& d3,
                                      uint32_t a0, uint32_t a1, uint32_t a2, uint32_t a3,
                                      uint32_t b0, uint32_t b1) {
    asm volatile("mma.sync.aligned.m16n8k16.row.col.f32.f16.f16.f32 "
                 "{%0,%1,%2,%3}, {%4,%5,%6,%7}, {%8,%9}, {%0,%1,%2,%3};"
                 : "+f"(d0), "+f"(d1), "+f"(d2), "+f"(d3)
                 : "r"(a0), "r"(a1), "r"(a2), "r"(a3), "r"(b0), "r"(b1));
}

// ---------------- kernel 1: merged conversions (R14) ----------------
#define NZBLK 65536
#define NDBLK 16384
__global__ __launch_bounds__(256) void conv_all(const float* __restrict__ z,
                                                const float* __restrict__ Dm,
                                                float* __restrict__ outz) {
    const int b = blockIdx.x;
    if (b < NZBLK) {
        const size_t t = (size_t)b * 256 + threadIdx.x;
        const size_t base = t * 8;
        const float4* src = reinterpret_cast<const float4*>(z + base);
        float4 v0 = __ldcs(src + 0);           // read-once: don't pollute L2
        float4 v1 = __ldcs(src + 1);
        float4* dst = reinterpret_cast<float4*>(outz + base);
        __stcs(dst + 0, v0);                   // write-once, never re-read
        __stcs(dst + 1, v1);
        __half2 h[4];
        h[0] = __floats2half2_rn(v0.x, v0.y);
        h[1] = __floats2half2_rn(v0.z, v0.w);
        h[2] = __floats2half2_rn(v1.x, v1.y);
        h[3] = __floats2half2_rn(v1.z, v1.w);
        *reinterpret_cast<uint4*>(g_zh + base) = *reinterpret_cast<uint4*>(h);
    } else {
        __shared__ __half t[64][65];
        const int db = b - NZBLK;              // 0..16383 = 128 kb x 128 nb
        const int kb = (db & 127) * 64, nb = (db >> 7) * 64;
        const int c = threadIdx.x & 63, rq = threadIdx.x >> 6;
#pragma unroll
        for (int i = 0; i < 16; ++i) {
            int r = i * 4 + rq;
            t[r][c] = __float2half_rn(__ldcs(Dm + (size_t)(kb + r) * NZ + nb + c));
        }
        __syncthreads();
#pragma unroll
        for (int i = 0; i < 16; ++i) {
            int r = i * 4 + rq;
            g_Dt[(size_t)(nb + r) * NZ + kb + c] = t[c][r];
        }
    }
}

// ---------------- kernel 2: fused GEMM + per-tile sum-of-squares (half-grid) ----------------
// grid 4096 = 64 m-tiles x 64 n-tiles; m = m0 + local. n in 2 groups of 32 for L2 reuse.
__global__ __launch_bounds__(256, 2) void gemm_k(int m0) {
    extern __shared__ unsigned char smem[];
    const uint32_t smem_b = smem_u32(smem);

    const int g = blockIdx.x;
    const int ng = g >> 11;               // 0..1  (n-group of 32)
    const int rem = g & 2047;
    const int m = m0 + (rem >> 5);        // m0..m0+63
    const int n = ng * 32 + (rem & 31);   // 0..63

    const int tid = threadIdx.x;
    const int wid = tid >> 5;
    const int lane = tid & 31;
    const int wm = wid & 1;
    const int wn = wid >> 1;
    const int lt = lane >> 3;       // ldmatrix tile id 0..3
    const int lr = lane & 7;

    const __half* gA = g_zh + (size_t)m * 128 * NZ;
    const __half* gB = g_Dt + (size_t)n * 128 * NZ;

    // A (row-major [m][k]): lt0 r0-7/k0-7, lt1 r8-15/k0-7, lt2 r0-7/k8-15, lt3 r8-15/k8-15
    const uint32_t aOff = (uint32_t)((wm * 64 + (lt & 1) * 8 + lr) * LDB + (lt >> 1) * 16);
    // B ([n][k] storage, NON-trans): lt0 n0-7/k0-7, lt1 n0-7/k8-15, lt2 n8-15/k0-7, lt3 n8-15/k8-15
    const uint32_t bOff = (uint32_t)((wn * 32 + (lt >> 1) * 8 + lr) * LDB + (lt & 1) * 16);

    float accf[4][4][4];            // fp32 accumulators: [mi][ni][d0..d3]
#pragma unroll
    for (int i = 0; i < 4; ++i)
#pragma unroll
        for (int j = 0; j < 4; ++j)
#pragma unroll
            for (int e = 0; e < 4; ++e) accf[i][j][e] = 0.0f;

    auto issue_load = [&](int kc, int st) {
        const uint32_t sA = smem_b + st * STAGE_BYTES;
        const uint32_t sB = sA + TILE_BYTES;
        const __half* pa = gA + kc * 64;
        const __half* pb = gB + kc * 64;
#pragma unroll
        for (int i = 0; i < 4; ++i) {
            int c = tid + i * 256;
            int row = c >> 3, seg = c & 7;
            cpasync16(sA + row * LDB + seg * 16, pa + (size_t)row * NZ + seg * 8);
            cpasync16(sB + row * LDB + seg * 16, pb + (size_t)row * NZ + seg * 8);
        }
    };

    // prologue: chunk 0 in flight
    issue_load(0, 0); CP_COMMIT();

#pragma unroll 1
    for (int kc = 0; kc < NK; ++kc) {
        CP_WAIT0();                 // own copies of chunk kc complete
        __syncthreads();            // all warps finished compute(kc-1); chunk-kc data visible
        if (kc + 1 < NK) { issue_load(kc + 1, (kc + 1) & 1); }
        CP_COMMIT();

        const int st = kc & 1;
        const uint32_t sA = smem_b + st * STAGE_BYTES + aOff;
        const uint32_t sB = smem_b + st * STAGE_BYTES + TILE_BYTES + bOff;

#pragma unroll
        for (int ks = 0; ks < 4; ++ks) {
            uint32_t a[4][4];
#pragma unroll
            for (int mi = 0; mi < 4; ++mi)
                ldsm4(a[mi][0], a[mi][1], a[mi][2], a[mi][3], sA + mi * (16 * LDB) + ks * 32);
            uint32_t b[4][2];
            ldsm4(b[0][0], b[0][1], b[1][0], b[1][1], sB + ks * 32);
            ldsm4(b[2][0], b[2][1], b[3][0], b[3][1], sB + 16 * LDB + ks * 32);
#pragma unroll
            for (int mi = 0; mi < 4; ++mi)
#pragma unroll
                for (int ni = 0; ni < 4; ++ni)
                    mma_f(accf[mi][ni][0], accf[mi][ni][1], accf[mi][ni][2], accf[mi][ni][3],
                          a[mi][0], a[mi][1], a[mi][2], a[mi][3], b[ni][0], b[ni][1]);
        }
        // no end-of-loop barrier: top wait0+BAR of next iteration orders everything
    }

    // ---- epilogue: per-row sum of squares from fragments ----
    __syncthreads();                               // drain reads before smem reuse
    float* red = reinterpret_cast<float*>(smem);   // [128][4]
#pragma unroll
    for (int mi = 0; mi < 4; ++mi) {
        float slo = 0.0f, shi = 0.0f;
#pragma unroll
        for (int ni = 0; ni < 4; ++ni) {
            slo = fmaf(accf[mi][ni][0], accf[mi][ni][0], slo);
            slo = fmaf(accf[mi][ni][1], accf[mi][ni][1], slo);
            shi = fmaf(accf[mi][ni][2], accf[mi][ni][2], shi);
            shi = fmaf(accf[mi][ni][3], accf[mi][ni][3], shi);
        }
        slo += __shfl_xor_sync(0xffffffffu, slo, 1);
        slo += __shfl_xor_sync(0xffffffffu, slo, 2);
        shi += __shfl_xor_sync(0xffffffffu, shi, 1);
        shi += __shfl_xor_sync(0xffffffffu, shi, 2);
        if ((lane & 3) == 0) {
            int row = wm * 64 + mi * 16 + (lane >> 2);
            red[row * 4 + wn] = slo;
            red[(row + 8) * 4 + wn] = shi;
        }
    }
    __syncthreads();
    if (tid < 128) {
        float s = red[tid * 4 + 0] + red[tid * 4 + 1] + red[tid * 4 + 2] + red[tid * 4 + 3];
        g_part[(size_t)(m * 128 + tid) * 64 + n] = s;
    }
}

// ---------------- kernel 3: finalize s = (s + eta*d) / rowsum ----------------
__global__ __launch_bounds__(256) void fin_k(float* __restrict__ outs) {
    const int row = blockIdx.x * 256 + threadIdx.x;
    const float4* p = reinterpret_cast<const float4*>(g_part + (size_t)row * 64);
    float s[16];
    float sum = 0.0f;
#pragma unroll
    for (int c = 0; c < 16; ++c) {
        float4 v = p[c];
        s[c] = v.x + v.y + v.z + v.w + 2560.0f;   // + ETA * D_SUB
        sum += s[c];
    }
    const float inv = 1.0f / sum;
    float4* op = reinterpret_cast<float4*>(outs + (size_t)row * NCLU);
#pragma unroll
    for (int q = 0; q < 4; ++q)
        op[q] = make_float4(s[4 * q] * inv, s[4 * q + 1] * inv, s[4 * q + 2] * inv, s[4 * q + 3] * inv);
}

// ---------------- launch ----------------
extern "C" void kernel_launch(void* const* d_in, const int* in_sizes, int n_in,
                              void* d_out, int out_size) {
    const float* z  = (const float*)d_in[0];
    const float* Dm = (const float*)d_in[1];
    float* out = (float*)d_out;

    cudaFuncSetAttribute(gemm_k, cudaFuncAttributeMaxDynamicSharedMemorySize, GEMM_SMEM);

    conv_all<<<NZBLK + NDBLK, 256>>>(z, Dm, out + (size_t)NROWS * NCLU);
    gemm_k<<<4096, 256, GEMM_SMEM>>>(0);    // m-tiles 0..63
    gemm_k<<<4096, 256, GEMM_SMEM>>>(64);   // m-tiles 64..127
    fin_k<<<NROWS / 256, 256>>>(out);
}